// round 2
// baseline (speedup 1.0000x reference)
#include <cuda_runtime.h>

#define NNODES 100000
#define TT 7
#define KK 10
#define DD 7
#define OO 32
#define HET ((TT + 1) * DD)   // 56
#define BLOCK 128
#define GRID ((NNODES + BLOCK - 1) / BLOCK)   // 782

// deterministic per-block partial sums (no device-side malloc allowed)
__device__ float g_partial[GRID * OO];

__global__ __launch_bounds__(BLOCK) void hetgcn_main(
    const float* __restrict__ x_node,      // [N, D]
    const float* __restrict__ x_het,       // [T, N, K, D]
    const int*   __restrict__ node_types,  // [N]
    const float* __restrict__ W_content,   // [T, D, D]  (t, o, d)
    const float* __restrict__ b_content,   // [T, D]
    const float* __restrict__ W_agg,       // [O, HET]
    const float* __restrict__ b_agg)       // [O]
{
    __shared__ float sx[BLOCK * KK * DD];   // 35840 B, staged x_het tile
    __shared__ float sW[TT * DD * DD];      // 343
    __shared__ float sb[TT * DD];           // 49
    __shared__ float sWagg[OO * HET];       // 1792
    __shared__ float sbagg[OO];
    __shared__ float wsum[4][OO];           // per-warp partials

    const int tid = threadIdx.x;
    const int n0  = blockIdx.x * BLOCK;
    const int n   = n0 + tid;
    const bool active = (n < NNODES);

    // stage weights to SMEM (broadcast-read later)
    for (int i = tid; i < TT * DD * DD; i += BLOCK) sW[i] = W_content[i];
    for (int i = tid; i < TT * DD;     i += BLOCK) sb[i] = b_content[i];
    for (int i = tid; i < OO * HET;    i += BLOCK) sWagg[i] = W_agg[i];
    if (tid < OO) sbagg[tid] = b_agg[tid];

    float het[HET];

    const int rows    = min(BLOCK, NNODES - n0);     // valid nodes in block
    const int tile_f2 = rows * (KK * DD) / 2;        // valid float2 count

    #pragma unroll
    for (int t = 0; t < TT; ++t) {
        __syncthreads();   // protect sx reuse from previous t
        // coalesced stage of x_het[t, n0:n0+rows, :, :]  (70 floats/node, 8B aligned)
        {
            const float2* src = (const float2*)(x_het + ((size_t)t * NNODES + n0) * (KK * DD));
            float2* dst = (float2*)sx;
            #pragma unroll
            for (int i = 0; i < (BLOCK * KK * DD / 2) / BLOCK; ++i) {   // 35 iters
                int idx = tid + i * BLOCK;
                if (idx < tile_f2) dst[idx] = src[idx];
            }
        }
        __syncthreads();

        // W_t, b_t in registers (saves ~3k broadcast LDS per thread)
        float Wr[DD * DD], br[DD];
        #pragma unroll
        for (int i = 0; i < DD * DD; ++i) Wr[i] = sW[t * DD * DD + i];
        #pragma unroll
        for (int i = 0; i < DD; ++i) br[i] = sb[t * DD + i];

        float acc[DD];
        #pragma unroll
        for (int o = 0; o < DD; ++o) acc[o] = 0.f;
        float cnt = 0.f;

        #pragma unroll 2
        for (int k = 0; k < KK; ++k) {
            float xv[DD];
            #pragma unroll
            for (int d = 0; d < DD; ++d) xv[d] = sx[tid * (KK * DD) + k * DD + d];
            float e[DD];
            bool nz = false;
            #pragma unroll
            for (int o = 0; o < DD; ++o) {
                float z = br[o];
                #pragma unroll
                for (int d = 0; d < DD; ++d) z = fmaf(xv[d], Wr[o * DD + d], z);
                e[o] = (z >= 0.f) ? z : 0.01f * z;    // LeakyReLU, exact semantics
                nz = nz || (e[o] != 0.f);
            }
            if (nz) cnt += 1.f;
            // masked-out rows are exactly all-zero, so unconditional sum == masked sum
            #pragma unroll
            for (int o = 0; o < DD; ++o) acc[o] += e[o];
        }
        const float inv = 1.f / fmaxf(cnt, 1.f);
        #pragma unroll
        for (int o = 0; o < DD; ++o) het[t * DD + o] = acc[o] * inv;
    }

    // self embedding with the node's own type-specific linear
    {
        const int ty = active ? node_types[n] : 0;
        float xn[DD];
        #pragma unroll
        for (int d = 0; d < DD; ++d) xn[d] = active ? x_node[n * DD + d] : 0.f;
        #pragma unroll
        for (int o = 0; o < DD; ++o) {
            float z = sb[ty * DD + o];
            #pragma unroll
            for (int d = 0; d < DD; ++d) z = fmaf(xn[d], sW[ty * DD * DD + o * DD + d], z);
            het[TT * DD + o] = (z >= 0.f) ? z : 0.01f * z;
        }
    }

    // final GEMV (56 -> 32) + sigmoid + warp butterfly reduction
    const float4* w4 = (const float4*)sWagg;
    const int wid = tid >> 5, lane = tid & 31;
    for (int o = 0; o < OO; ++o) {
        float z = sbagg[o];
        #pragma unroll
        for (int j = 0; j < HET / 4; ++j) {          // 14 float4 broadcast loads
            float4 w = w4[o * (HET / 4) + j];
            z = fmaf(het[4 * j + 0], w.x, z);
            z = fmaf(het[4 * j + 1], w.y, z);
            z = fmaf(het[4 * j + 2], w.z, z);
            z = fmaf(het[4 * j + 3], w.w, z);
        }
        float y = active ? (1.f / (1.f + __expf(-z))) : 0.f;
        #pragma unroll
        for (int off = 16; off > 0; off >>= 1)
            y += __shfl_xor_sync(0xffffffffu, y, off);
        if (lane == 0) wsum[wid][o] = y;
    }
    __syncthreads();
    if (tid < OO) {
        float p = wsum[0][tid] + wsum[1][tid] + wsum[2][tid] + wsum[3][tid];
        g_partial[blockIdx.x * OO + tid] = p;   // deterministic, no atomics
    }
}

// deterministic final reduction: out[o] = mean over nodes
__global__ void hetgcn_reduce(float* __restrict__ out)
{
    __shared__ float s[256];
    const int o = threadIdx.x & 31;
    const int g = threadIdx.x >> 5;          // 8 groups of 32
    float acc = 0.f;
    for (int b = g; b < GRID; b += 8)
        acc += g_partial[b * OO + o];
    s[threadIdx.x] = acc;
    __syncthreads();
    if (threadIdx.x < OO) {
        float a = 0.f;
        #pragma unroll
        for (int gg = 0; gg < 8; ++gg) a += s[gg * 32 + o];
        out[o] = a * (1.0f / (float)NNODES);
    }
}

extern "C" void kernel_launch(void* const* d_in, const int* in_sizes, int n_in,
                              void* d_out, int out_size)
{
    const float* x_node    = (const float*)d_in[0];   // [N, D]
    const float* x_het     = (const float*)d_in[1];   // [T, N, K, D]
    const int*   types     = (const int*)  d_in[2];   // [N]
    const float* W_content = (const float*)d_in[3];   // [T, D, D]
    const float* b_content = (const float*)d_in[4];   // [T, D]
    const float* W_agg     = (const float*)d_in[5];   // [O, 56]
    const float* b_agg     = (const float*)d_in[6];   // [O]
    float* out = (float*)d_out;

    hetgcn_main<<<GRID, BLOCK>>>(x_node, x_het, types, W_content, b_content, W_agg, b_agg);
    hetgcn_reduce<<<1, 256>>>(out);
}

// round 3
// speedup vs baseline: 1.3507x; 1.3507x over previous
#include <cuda_runtime.h>
#include <cstdint>

#define NNODES 100000
#define TT 7
#define KK 10
#define DD 7
#define OO 32
#define HET ((TT + 1) * DD)        // 56
#define BLOCK 128
#define GRID ((NNODES + BLOCK - 1) / BLOCK)   // 782
#define NODE_F (KK * DD)           // 70 floats per node per type
#define TILE_F (BLOCK * NODE_F)    // 8960 floats = 35840 B per tile

// deterministic per-block partial sums (no device-side malloc allowed)
__device__ float g_partial[GRID * OO];

__device__ __forceinline__ void cp_async16(uint32_t smem, const void* gmem) {
    asm volatile("cp.async.ca.shared.global [%0], [%1], 16;\n" :: "r"(smem), "l"(gmem));
}
__device__ __forceinline__ void cp_commit() {
    asm volatile("cp.async.commit_group;\n" ::: "memory");
}
template <int N>
__device__ __forceinline__ void cp_wait() {
    asm volatile("cp.async.wait_group %0;\n" :: "n"(N) : "memory");
}

__global__ __launch_bounds__(BLOCK) void hetgcn_main(
    const float* __restrict__ x_node,      // [N, D]
    const float* __restrict__ x_het,       // [T, N, K, D]
    const int*   __restrict__ node_types,  // [N]
    const float* __restrict__ W_content,   // [T, D, D]
    const float* __restrict__ b_content,   // [T, D]
    const float* __restrict__ W_agg,       // [O, HET]
    const float* __restrict__ b_agg)       // [O]
{
    __shared__ __align__(16) float sx[2][TILE_F];   // double-buffered tile (71680 B)
    __shared__ float sW[TT * DD * DD];
    __shared__ float sb[TT * DD];
    __shared__ __align__(16) float sWagg[OO * HET];
    __shared__ float sbagg[OO];
    __shared__ float wsum[4][OO];

    const int tid = threadIdx.x;
    const int n0  = blockIdx.x * BLOCK;
    const int n   = n0 + tid;
    const bool active = (n < NNODES);
    const int rows   = min(BLOCK, NNODES - n0);
    const int chunks = rows * NODE_F / 4;           // 16B chunks (rows always even)

    // stage weights to SMEM (covered by the first __syncthreads below)
    for (int i = tid; i < TT * DD * DD; i += BLOCK) sW[i] = W_content[i];
    for (int i = tid; i < TT * DD;     i += BLOCK) sb[i] = b_content[i];
    for (int i = tid; i < OO * HET;    i += BLOCK) sWagg[i] = W_agg[i];
    if (tid < OO) sbagg[tid] = b_agg[tid];

    // prefetch tile 0
    {
        const float* src = x_het + (size_t)n0 * NODE_F;
        uint32_t dst = (uint32_t)__cvta_generic_to_shared(&sx[0][0]);
        for (int c = tid; c < chunks; c += BLOCK)
            cp_async16(dst + c * 16, src + c * 4);
        cp_commit();
    }

    float het[HET];

    #pragma unroll
    for (int t = 0; t < TT; ++t) {
        // prefetch tile t+1 into the other buffer
        if (t + 1 < TT) {
            const float* src = x_het + ((size_t)(t + 1) * NNODES + n0) * NODE_F;
            uint32_t dst = (uint32_t)__cvta_generic_to_shared(&sx[(t + 1) & 1][0]);
            for (int c = tid; c < chunks; c += BLOCK)
                cp_async16(dst + c * 16, src + c * 4);
            cp_commit();
        }
        if (t + 1 < TT) cp_wait<1>(); else cp_wait<0>();
        __syncthreads();   // tile t landed for all threads (+weights on t==0)

        // W_t, b_t in registers (broadcast-free inner loop)
        float Wr[DD * DD], br[DD];
        #pragma unroll
        for (int i = 0; i < DD * DD; ++i) Wr[i] = sW[t * DD * DD + i];
        #pragma unroll
        for (int i = 0; i < DD; ++i) br[i] = sb[t * DD + i];

        float acc[DD];
        #pragma unroll
        for (int o = 0; o < DD; ++o) acc[o] = 0.f;
        float cnt = 0.f;

        const float* xs = &sx[t & 1][tid * NODE_F];
        #pragma unroll 2
        for (int k = 0; k < KK; ++k) {
            float xv[DD];
            #pragma unroll
            for (int d = 0; d < DD; ++d) xv[d] = xs[k * DD + d];
            float e[DD];
            bool nz = false;
            #pragma unroll
            for (int o = 0; o < DD; ++o) {
                float z = br[o];
                #pragma unroll
                for (int d = 0; d < DD; ++d) z = fmaf(xv[d], Wr[o * DD + d], z);
                e[o] = (z >= 0.f) ? z : 0.01f * z;   // LeakyReLU (exact ref semantics)
                nz = nz || (e[o] != 0.f);
            }
            if (nz) cnt += 1.f;
            // masked-out rows are exactly all-zero -> unconditional sum == masked sum
            #pragma unroll
            for (int o = 0; o < DD; ++o) acc[o] += e[o];
        }
        const float inv = 1.f / fmaxf(cnt, 1.f);
        #pragma unroll
        for (int o = 0; o < DD; ++o) het[t * DD + o] = acc[o] * inv;

        __syncthreads();   // all threads done reading buf (t&1) before it is re-filled
    }

    // self embedding with the node's own type-specific linear
    {
        const int ty = active ? node_types[n] : 0;
        float xn[DD];
        #pragma unroll
        for (int d = 0; d < DD; ++d) xn[d] = active ? x_node[n * DD + d] : 0.f;
        #pragma unroll
        for (int o = 0; o < DD; ++o) {
            float z = sb[ty * DD + o];
            #pragma unroll
            for (int d = 0; d < DD; ++d) z = fmaf(xn[d], sW[ty * DD * DD + o * DD + d], z);
            het[TT * DD + o] = (z >= 0.f) ? z : 0.01f * z;
        }
    }

    // final GEMV (56 -> 32) + sigmoid + warp butterfly reduction
    const float4* w4 = (const float4*)sWagg;
    const int wid = tid >> 5, lane = tid & 31;
    for (int o = 0; o < OO; ++o) {
        float z = sbagg[o];
        #pragma unroll
        for (int j = 0; j < HET / 4; ++j) {
            float4 w = w4[o * (HET / 4) + j];
            z = fmaf(het[4 * j + 0], w.x, z);
            z = fmaf(het[4 * j + 1], w.y, z);
            z = fmaf(het[4 * j + 2], w.z, z);
            z = fmaf(het[4 * j + 3], w.w, z);
        }
        float y = active ? (1.f / (1.f + __expf(-z))) : 0.f;
        #pragma unroll
        for (int off = 16; off > 0; off >>= 1)
            y += __shfl_xor_sync(0xffffffffu, y, off);
        if (lane == 0) wsum[wid][o] = y;
    }
    __syncthreads();
    if (tid < OO) {
        float p = wsum[0][tid] + wsum[1][tid] + wsum[2][tid] + wsum[3][tid];
        g_partial[blockIdx.x * OO + tid] = p;   // deterministic, no atomics
    }
}

// deterministic final reduction: out[o] = mean over nodes
// 1024 threads = 32 groups x 32 outputs -> only ~25 strided loads per thread
__global__ __launch_bounds__(1024) void hetgcn_reduce(float* __restrict__ out)
{
    __shared__ float s[1024];
    const int o = threadIdx.x & 31;
    const int g = threadIdx.x >> 5;          // 32 groups
    float a0 = 0.f, a1 = 0.f;
    int b = g;
    // 2-way ILP accumulation over ~25 iterations
    for (; b + 32 < GRID; b += 64) {
        a0 += g_partial[b * OO + o];
        a1 += g_partial[(b + 32) * OO + o];
    }
    if (b < GRID) a0 += g_partial[b * OO + o];
    s[threadIdx.x] = a0 + a1;
    __syncthreads();
    #pragma unroll
    for (int stride = 16; stride > 0; stride >>= 1) {
        if (g < stride)
            s[g * 32 + o] += s[(g + stride) * 32 + o];
        __syncthreads();
    }
    if (threadIdx.x < OO)
        out[threadIdx.x] = s[threadIdx.x] * (1.0f / (float)NNODES);
}

extern "C" void kernel_launch(void* const* d_in, const int* in_sizes, int n_in,
                              void* d_out, int out_size)
{
    const float* x_node    = (const float*)d_in[0];   // [N, D]
    const float* x_het     = (const float*)d_in[1];   // [T, N, K, D]
    const int*   types     = (const int*)  d_in[2];   // [N]
    const float* W_content = (const float*)d_in[3];   // [T, D, D]
    const float* b_content = (const float*)d_in[4];   // [T, D]
    const float* W_agg     = (const float*)d_in[5];   // [O, 56]
    const float* b_agg     = (const float*)d_in[6];   // [O]
    float* out = (float*)d_out;

    hetgcn_main<<<GRID, BLOCK>>>(x_node, x_het, types, W_content, b_content, W_agg, b_agg);
    hetgcn_reduce<<<1, 1024>>>(out);
}